// round 13
// baseline (speedup 1.0000x reference)
#include <cuda_runtime.h>
#include <cuda_fp16.h>
#include <cstdint>
#include <cstddef>

// out[t,n] = sum_k X[t,k] * W'[n,k]
// W'[n, g*128+k] = (norm[n,g]/sqrt(128)) * sum_j rot[g,j,k] * cb[nib(idx[n, g*128+j])]
// Rotation folded into token-independent weights; GEMM on HMMA fp16/fp32-acc.
// (tcgen05 unavailable: harness PTX targets compute_103 without the 'a' feature set.)

#define T_TOK 8192
#define KDIM  4096
#define NDIM  4096

__device__ __align__(1024) __half g_Xh[(size_t)T_TOK * KDIM]; // 64 MiB
__device__ __align__(1024) __half g_Wh[(size_t)NDIM * KDIM];  // 32 MiB

// ---------------- helpers ----------------
__device__ __forceinline__ uint32_t smem_u32(const void* p) {
    uint32_t a;
    asm("{ .reg .u64 t; cvta.to.shared.u64 t, %1; cvt.u32.u64 %0, t; }" : "=r"(a) : "l"(p));
    return a;
}
__device__ __forceinline__ void cp_async16(uint32_t s, const void* g) {
    asm volatile("cp.async.cg.shared.global [%0], [%1], 16;" :: "r"(s), "l"(g) : "memory");
}
__device__ __forceinline__ void cp_commit() { asm volatile("cp.async.commit_group;" ::: "memory"); }
template <int N> __device__ __forceinline__ void cp_wait() {
    asm volatile("cp.async.wait_group %0;" :: "n"(N) : "memory");
}
__device__ __forceinline__ void ldsm4(uint32_t* r, uint32_t addr) {
    asm volatile("ldmatrix.sync.aligned.m8n8.x4.shared.b16 {%0,%1,%2,%3}, [%4];"
                 : "=r"(r[0]), "=r"(r[1]), "=r"(r[2]), "=r"(r[3]) : "r"(addr));
}
__device__ __forceinline__ void mma16816(float* c, const uint32_t* a, const uint32_t* b) {
    asm volatile(
        "mma.sync.aligned.m16n8k16.row.col.f32.f16.f16.f32 "
        "{%0,%1,%2,%3}, {%4,%5,%6,%7}, {%8,%9}, {%0,%1,%2,%3};"
        : "+f"(c[0]), "+f"(c[1]), "+f"(c[2]), "+f"(c[3])
        : "r"(a[0]), "r"(a[1]), "r"(a[2]), "r"(a[3]), "r"(b[0]), "r"(b[1]));
}

// ---------------- kernel 1: X fp32 -> fp16 (73% HBM spec; leave it) ----------------
__global__ void convert_x_kernel(const float* __restrict__ x) {
    size_t i = (size_t)blockIdx.x * blockDim.x + threadIdx.x;
    const size_t stride = (size_t)gridDim.x * blockDim.x;
    const size_t n4 = (size_t)T_TOK * KDIM / 4;
    const float4* x4 = (const float4*)x;
    uint2* o = (uint2*)g_Xh;
    for (; i < n4; i += stride) {
        float4 v = x4[i];
        __half2 a = __floats2half2_rn(v.x, v.y);
        __half2 b = __floats2half2_rn(v.z, v.w);
        uint2 u;
        u.x = *(const uint32_t*)&a;
        u.y = *(const uint32_t*)&b;
        o[i] = u;
    }
}

// ---------------- kernel 2: build W' (unchanged, known good) ----------------
__global__ __launch_bounds__(256) void build_w_kernel(
    const int* __restrict__ idxp, const float* __restrict__ cb,
    const float* __restrict__ norms, const float* __restrict__ rot) {
    __shared__ float rot_s[64 * 128];
    __shared__ __half wc[32 * 128];
    __shared__ float cb_s[16];

    const int tid = threadIdx.x;
    const int g = blockIdx.y;
    const int n0 = blockIdx.x * 32;

    if (tid < 16) cb_s[tid] = cb[tid];
    __syncthreads();

    {
        const int row = tid >> 3, c = tid & 7;
        const int n = n0 + row;
        const float scale = norms[n * 32 + g] * 0.08838834764831845f;
        const int4* p = (const int4*)(idxp + (size_t)n * 2048 + g * 64 + c * 8);
        int4 v0 = p[0], v1 = p[1];
        int vs[8] = {v0.x, v0.y, v0.z, v0.w, v1.x, v1.y, v1.z, v1.w};
#pragma unroll
        for (int i = 0; i < 8; i++) {
            int j = c * 16 + i * 2;
            wc[row * 128 + j]     = __float2half(cb_s[vs[i] & 15] * scale);
            wc[row * 128 + j + 1] = __float2half(cb_s[(vs[i] >> 4) & 15] * scale);
        }
    }

    const int rq = tid >> 4;
    const int k0 = (tid & 15) * 8;
    float acc0[8], acc1[8];
#pragma unroll
    for (int i = 0; i < 8; i++) { acc0[i] = 0.f; acc1[i] = 0.f; }

    for (int jt = 0; jt < 2; jt++) {
        __syncthreads();
        const float4* gr = (const float4*)(rot + (size_t)g * 16384 + (size_t)jt * 8192);
        float4* rs4 = (float4*)rot_s;
#pragma unroll
        for (int i = 0; i < 8; i++) rs4[tid + i * 256] = gr[tid + i * 256];
        __syncthreads();
#pragma unroll 8
        for (int j = 0; j < 64; j++) {
            float w0 = __half2float(wc[rq * 128 + jt * 64 + j]);
            float w1 = __half2float(wc[(rq + 16) * 128 + jt * 64 + j]);
            float4 r0 = *(const float4*)&rot_s[j * 128 + k0];
            float4 r1 = *(const float4*)&rot_s[j * 128 + k0 + 4];
            acc0[0] += w0 * r0.x; acc0[1] += w0 * r0.y; acc0[2] += w0 * r0.z; acc0[3] += w0 * r0.w;
            acc0[4] += w0 * r1.x; acc0[5] += w0 * r1.y; acc0[6] += w0 * r1.z; acc0[7] += w0 * r1.w;
            acc1[0] += w1 * r0.x; acc1[1] += w1 * r0.y; acc1[2] += w1 * r0.z; acc1[3] += w1 * r0.w;
            acc1[4] += w1 * r1.x; acc1[5] += w1 * r1.y; acc1[6] += w1 * r1.z; acc1[7] += w1 * r1.w;
        }
    }

    {
        __half2 h0 = __floats2half2_rn(acc0[0], acc0[1]);
        __half2 h1 = __floats2half2_rn(acc0[2], acc0[3]);
        __half2 h2 = __floats2half2_rn(acc0[4], acc0[5]);
        __half2 h3 = __floats2half2_rn(acc0[6], acc0[7]);
        uint4 u = {*(uint32_t*)&h0, *(uint32_t*)&h1, *(uint32_t*)&h2, *(uint32_t*)&h3};
        *(uint4*)&g_Wh[(size_t)(n0 + rq) * KDIM + g * 128 + k0] = u;
    }
    {
        __half2 h0 = __floats2half2_rn(acc1[0], acc1[1]);
        __half2 h1 = __floats2half2_rn(acc1[2], acc1[3]);
        __half2 h2 = __floats2half2_rn(acc1[4], acc1[5]);
        __half2 h3 = __floats2half2_rn(acc1[6], acc1[7]);
        uint4 u = {*(uint32_t*)&h0, *(uint32_t*)&h1, *(uint32_t*)&h2, *(uint32_t*)&h3};
        *(uint4*)&g_Wh[(size_t)(n0 + rq + 16) * KDIM + g * 128 + k0] = u;
    }
}

// ---------------- kernel 3: GEMM C[T,N] = Xh @ Wh^T ----------------
// CTA 128x256, 512 threads (16 warps 4x4), warp tile 32x64, KT=32,
// 3-stage cp.async(16B) pipeline, dynamic smem, 1 CTA/SM.
#define LDT 40                     // 80B row stride: conflict-free ldsm, 16B-aligned
#define KT  32
#define NKT (KDIM / KT)            // 128
#define A_HALFS (128 * LDT)        // per stage
#define B_HALFS (256 * LDT)
#define STAGE_HALFS (A_HALFS + B_HALFS)
#define NSTAGE 3
#define GEMM_SMEM (NSTAGE * STAGE_HALFS * 2)  // 92160 B

__device__ __forceinline__ void load_tile(__half* sbase, const __half* __restrict__ gA,
                                          const __half* __restrict__ gB, int kt, int tid) {
    __half* sA = sbase;
    __half* sB = sbase + A_HALFS;
    // A: 128 rows x 4 chunks(16B=8 halfs) = 512 units; 1 per thread
    {
        int row = tid >> 2, c = tid & 3;
        cp_async16(smem_u32(&sA[row * LDT + c * 8]), gA + (size_t)row * KDIM + kt * KT + c * 8);
    }
    // B: 256 rows x 4 chunks = 1024 units; 2 per thread
#pragma unroll
    for (int i = 0; i < 2; i++) {
        int u = tid + i * 512;
        int row = u >> 2, c = u & 3;
        cp_async16(smem_u32(&sB[row * LDT + c * 8]), gB + (size_t)row * KDIM + kt * KT + c * 8);
    }
}

__global__ __launch_bounds__(512, 1) void gemm_kernel(float* __restrict__ C) {
    extern __shared__ __half smem[];

    const int tid = threadIdx.x;
    const int wid = tid >> 5, lane = tid & 31;
    const int warpM = (wid >> 2) * 32;  // 4 warp-rows  -> 128
    const int warpN = (wid & 3) * 64;   // 4 warp-cols  -> 256
    const size_t bm = (size_t)blockIdx.y * 128;
    const size_t bn = (size_t)blockIdx.x * 256;

    const __half* gA = g_Xh + bm * KDIM;
    const __half* gB = g_Wh + bn * KDIM;

    float acc[2][8][4];
#pragma unroll
    for (int mi = 0; mi < 2; mi++)
#pragma unroll
        for (int ni = 0; ni < 8; ni++)
#pragma unroll
            for (int q = 0; q < 4; q++) acc[mi][ni][q] = 0.f;

    load_tile(smem + 0 * STAGE_HALFS, gA, gB, 0, tid); cp_commit();
    load_tile(smem + 1 * STAGE_HALFS, gA, gB, 1, tid); cp_commit();

    for (int kt = 0; kt < NKT; kt++) {
        if (kt + 1 < NKT) cp_wait<1>(); else cp_wait<0>();
        __syncthreads();   // stage kt ready; all warps done with stage kt-1 compute

        // prefetch stage kt+2 into buffer (kt+2)%3 == (kt-1)%3 (freed by the sync above)
        if (kt + 2 < NKT) {
            load_tile(smem + ((kt + 2) % NSTAGE) * STAGE_HALFS, gA, gB, kt + 2, tid);
            cp_commit();
        }

        const uint32_t a_base = smem_u32(smem + (kt % NSTAGE) * STAGE_HALFS);
        const uint32_t b_base = a_base + A_HALFS * 2;
#pragma unroll
        for (int kk = 0; kk < KT; kk += 16) {
            uint32_t af[2][4];
#pragma unroll
            for (int mi = 0; mi < 2; mi++) {
                int row = warpM + mi * 16 + (lane & 15);
                int col = kk + (lane >> 4) * 8;
                ldsm4(af[mi], a_base + (row * LDT + col) * 2);
            }
            uint32_t bf[4][4];
#pragma unroll
            for (int nj = 0; nj < 4; nj++) {
                int row = warpN + nj * 16 + (lane & 7) + ((lane >> 4) << 3);
                int col = kk + (((lane >> 3) & 1) << 3);
                ldsm4(bf[nj], b_base + (row * LDT + col) * 2);
            }
#pragma unroll
            for (int mi = 0; mi < 2; mi++)
#pragma unroll
                for (int ni = 0; ni < 8; ni++)
                    mma16816(acc[mi][ni], af[mi], &bf[ni >> 1][(ni & 1) * 2]);
        }
        __syncthreads();   // all warps done reading stage kt before it is refilled
    }

    // epilogue: fp32 out [T, N]
#pragma unroll
    for (int mi = 0; mi < 2; mi++) {
#pragma unroll
        for (int ni = 0; ni < 8; ni++) {
            size_t r = bm + warpM + mi * 16 + (lane >> 2);
            size_t col = bn + warpN + ni * 8 + (lane & 3) * 2;
            float2 lo = {acc[mi][ni][0], acc[mi][ni][1]};
            float2 hi = {acc[mi][ni][2], acc[mi][ni][3]};
            *(float2*)&C[r * NDIM + col] = lo;
            *(float2*)&C[(r + 8) * NDIM + col] = hi;
        }
    }
}

// ---------------- launch ----------------
extern "C" void kernel_launch(void* const* d_in, const int* in_sizes, int n_in,
                              void* d_out, int out_size) {
    const float* x     = (const float*)d_in[0];
    const int*   idxp  = (const int*)d_in[1];
    const float* cb    = (const float*)d_in[2];
    const float* norms = (const float*)d_in[3];
    const float* rot   = (const float*)d_in[4];
    float* out = (float*)d_out;

    cudaFuncSetAttribute(gemm_kernel, cudaFuncAttributeMaxDynamicSharedMemorySize, GEMM_SMEM);

    convert_x_kernel<<<4096, 256>>>(x);
    build_w_kernel<<<dim3(NDIM / 32, 32), 256>>>(idxp, cb, norms, rot);
    gemm_kernel<<<dim3(NDIM / 256, T_TOK / 128), 512, GEMM_SMEM>>>(out);
}

// round 16
// speedup vs baseline: 1.1297x; 1.1297x over previous
#include <cuda_runtime.h>
#include <cuda_fp16.h>
#include <cstdint>
#include <cstddef>

// out[t,n] = sum_k X[t,k] * W'[n,k]
// W'[n, g*128+k] = (norm[n,g]/sqrt(128)) * sum_j rot[g,j,k] * cb[nib(idx[n, g*128+j])]
// Rotation folded into token-independent weights; GEMM on HMMA fp16/fp32-acc.
// R13: back to CTA 128x128 @ 2 CTA/SM (R4's measured-good occupancy), with a
// 4-stage 16B cp.async pipeline (R12 showed 1 CTA/SM barrier coupling regresses).

#define T_TOK 8192
#define KDIM  4096
#define NDIM  4096

__device__ __align__(1024) __half g_Xh[(size_t)T_TOK * KDIM]; // 64 MiB
__device__ __align__(1024) __half g_Wh[(size_t)NDIM * KDIM];  // 32 MiB

// ---------------- helpers ----------------
__device__ __forceinline__ uint32_t smem_u32(const void* p) {
    uint32_t a;
    asm("{ .reg .u64 t; cvta.to.shared.u64 t, %1; cvt.u32.u64 %0, t; }" : "=r"(a) : "l"(p));
    return a;
}
__device__ __forceinline__ void cp_async16(uint32_t s, const void* g) {
    asm volatile("cp.async.cg.shared.global [%0], [%1], 16;" :: "r"(s), "l"(g) : "memory");
}
__device__ __forceinline__ void cp_commit() { asm volatile("cp.async.commit_group;" ::: "memory"); }
template <int N> __device__ __forceinline__ void cp_wait() {
    asm volatile("cp.async.wait_group %0;" :: "n"(N) : "memory");
}
__device__ __forceinline__ void ldsm4(uint32_t* r, uint32_t addr) {
    asm volatile("ldmatrix.sync.aligned.m8n8.x4.shared.b16 {%0,%1,%2,%3}, [%4];"
                 : "=r"(r[0]), "=r"(r[1]), "=r"(r[2]), "=r"(r[3]) : "r"(addr));
}
__device__ __forceinline__ void mma16816(float* c, const uint32_t* a, const uint32_t* b) {
    asm volatile(
        "mma.sync.aligned.m16n8k16.row.col.f32.f16.f16.f32 "
        "{%0,%1,%2,%3}, {%4,%5,%6,%7}, {%8,%9}, {%0,%1,%2,%3};"
        : "+f"(c[0]), "+f"(c[1]), "+f"(c[2]), "+f"(c[3])
        : "r"(a[0]), "r"(a[1]), "r"(a[2]), "r"(a[3]), "r"(b[0]), "r"(b[1]));
}

// ---------------- kernel 1: X fp32 -> fp16 (73% HBM spec; leave it) ----------------
__global__ void convert_x_kernel(const float* __restrict__ x) {
    size_t i = (size_t)blockIdx.x * blockDim.x + threadIdx.x;
    const size_t stride = (size_t)gridDim.x * blockDim.x;
    const size_t n4 = (size_t)T_TOK * KDIM / 4;
    const float4* x4 = (const float4*)x;
    uint2* o = (uint2*)g_Xh;
    for (; i < n4; i += stride) {
        float4 v = x4[i];
        __half2 a = __floats2half2_rn(v.x, v.y);
        __half2 b = __floats2half2_rn(v.z, v.w);
        uint2 u;
        u.x = *(const uint32_t*)&a;
        u.y = *(const uint32_t*)&b;
        o[i] = u;
    }
}

// ---------------- kernel 2: build W' (unchanged, known good) ----------------
__global__ __launch_bounds__(256) void build_w_kernel(
    const int* __restrict__ idxp, const float* __restrict__ cb,
    const float* __restrict__ norms, const float* __restrict__ rot) {
    __shared__ float rot_s[64 * 128];
    __shared__ __half wc[32 * 128];
    __shared__ float cb_s[16];

    const int tid = threadIdx.x;
    const int g = blockIdx.y;
    const int n0 = blockIdx.x * 32;

    if (tid < 16) cb_s[tid] = cb[tid];
    __syncthreads();

    {
        const int row = tid >> 3, c = tid & 7;
        const int n = n0 + row;
        const float scale = norms[n * 32 + g] * 0.08838834764831845f;
        const int4* p = (const int4*)(idxp + (size_t)n * 2048 + g * 64 + c * 8);
        int4 v0 = p[0], v1 = p[1];
        int vs[8] = {v0.x, v0.y, v0.z, v0.w, v1.x, v1.y, v1.z, v1.w};
#pragma unroll
        for (int i = 0; i < 8; i++) {
            int j = c * 16 + i * 2;
            wc[row * 128 + j]     = __float2half(cb_s[vs[i] & 15] * scale);
            wc[row * 128 + j + 1] = __float2half(cb_s[(vs[i] >> 4) & 15] * scale);
        }
    }

    const int rq = tid >> 4;
    const int k0 = (tid & 15) * 8;
    float acc0[8], acc1[8];
#pragma unroll
    for (int i = 0; i < 8; i++) { acc0[i] = 0.f; acc1[i] = 0.f; }

    for (int jt = 0; jt < 2; jt++) {
        __syncthreads();
        const float4* gr = (const float4*)(rot + (size_t)g * 16384 + (size_t)jt * 8192);
        float4* rs4 = (float4*)rot_s;
#pragma unroll
        for (int i = 0; i < 8; i++) rs4[tid + i * 256] = gr[tid + i * 256];
        __syncthreads();
#pragma unroll 8
        for (int j = 0; j < 64; j++) {
            float w0 = __half2float(wc[rq * 128 + jt * 64 + j]);
            float w1 = __half2float(wc[(rq + 16) * 128 + jt * 64 + j]);
            float4 r0 = *(const float4*)&rot_s[j * 128 + k0];
            float4 r1 = *(const float4*)&rot_s[j * 128 + k0 + 4];
            acc0[0] += w0 * r0.x; acc0[1] += w0 * r0.y; acc0[2] += w0 * r0.z; acc0[3] += w0 * r0.w;
            acc0[4] += w0 * r1.x; acc0[5] += w0 * r1.y; acc0[6] += w0 * r1.z; acc0[7] += w0 * r1.w;
            acc1[0] += w1 * r0.x; acc1[1] += w1 * r0.y; acc1[2] += w1 * r0.z; acc1[3] += w1 * r0.w;
            acc1[4] += w1 * r1.x; acc1[5] += w1 * r1.y; acc1[6] += w1 * r1.z; acc1[7] += w1 * r1.w;
        }
    }

    {
        __half2 h0 = __floats2half2_rn(acc0[0], acc0[1]);
        __half2 h1 = __floats2half2_rn(acc0[2], acc0[3]);
        __half2 h2 = __floats2half2_rn(acc0[4], acc0[5]);
        __half2 h3 = __floats2half2_rn(acc0[6], acc0[7]);
        uint4 u = {*(uint32_t*)&h0, *(uint32_t*)&h1, *(uint32_t*)&h2, *(uint32_t*)&h3};
        *(uint4*)&g_Wh[(size_t)(n0 + rq) * KDIM + g * 128 + k0] = u;
    }
    {
        __half2 h0 = __floats2half2_rn(acc1[0], acc1[1]);
        __half2 h1 = __floats2half2_rn(acc1[2], acc1[3]);
        __half2 h2 = __floats2half2_rn(acc1[4], acc1[5]);
        __half2 h3 = __floats2half2_rn(acc1[6], acc1[7]);
        uint4 u = {*(uint32_t*)&h0, *(uint32_t*)&h1, *(uint32_t*)&h2, *(uint32_t*)&h3};
        *(uint4*)&g_Wh[(size_t)(n0 + rq + 16) * KDIM + g * 128 + k0] = u;
    }
}

// ---------------- kernel 3: GEMM C[T,N] = Xh @ Wh^T ----------------
// CTA 128x128, 256 threads (8 warps 4x2), warp tile 32x64, KT=32,
// 4-stage cp.async(16B) pipeline, dynamic smem, 2 CTA/SM.
#define LDT 40                     // 80B row stride: conflict-free ldsm, 16B-aligned
#define KT  32
#define NKT (KDIM / KT)            // 128
#define A_HALFS (128 * LDT)
#define B_HALFS (128 * LDT)
#define STAGE_HALFS (A_HALFS + B_HALFS)       // 10240 halfs = 20480 B
#define NSTAGE 4
#define GEMM_SMEM (NSTAGE * STAGE_HALFS * 2)  // 81920 B (x2 CTA = 160 KB < 228 KB)

__device__ __forceinline__ void load_tile(__half* sbase, const __half* __restrict__ gA,
                                          const __half* __restrict__ gB, int kt, int tid) {
    __half* sA = sbase;
    __half* sB = sbase + A_HALFS;
    // A: 128 rows x 4 chunks(16B) = 512 units; 2 per thread
#pragma unroll
    for (int i = 0; i < 2; i++) {
        int u = tid + i * 256;
        int row = u >> 2, c = u & 3;
        cp_async16(smem_u32(&sA[row * LDT + c * 8]), gA + (size_t)row * KDIM + kt * KT + c * 8);
    }
    // B: 128 rows x 4 chunks = 512 units; 2 per thread
#pragma unroll
    for (int i = 0; i < 2; i++) {
        int u = tid + i * 256;
        int row = u >> 2, c = u & 3;
        cp_async16(smem_u32(&sB[row * LDT + c * 8]), gB + (size_t)row * KDIM + kt * KT + c * 8);
    }
}

__global__ __launch_bounds__(256, 2) void gemm_kernel(float* __restrict__ C) {
    extern __shared__ __half smem[];

    const int tid = threadIdx.x;
    const int wid = tid >> 5, lane = tid & 31;
    const int warpM = (wid >> 1) * 32;  // 4 warp-rows -> 128
    const int warpN = (wid & 1) * 64;   // 2 warp-cols -> 128
    const size_t bm = (size_t)blockIdx.y * 128;
    const size_t bn = (size_t)blockIdx.x * 128;

    const __half* gA = g_Xh + bm * KDIM;
    const __half* gB = g_Wh + bn * KDIM;

    float acc[2][8][4];
#pragma unroll
    for (int mi = 0; mi < 2; mi++)
#pragma unroll
        for (int ni = 0; ni < 8; ni++)
#pragma unroll
            for (int q = 0; q < 4; q++) acc[mi][ni][q] = 0.f;

    load_tile(smem + 0 * STAGE_HALFS, gA, gB, 0, tid); cp_commit();
    load_tile(smem + 1 * STAGE_HALFS, gA, gB, 1, tid); cp_commit();
    load_tile(smem + 2 * STAGE_HALFS, gA, gB, 2, tid); cp_commit();

    for (int kt = 0; kt < NKT; kt++) {
        // retire group kt: outstanding groups are kt .. min(kt+2, NKT-1)
        if (kt + 2 < NKT)      cp_wait<2>();
        else if (kt + 1 < NKT) cp_wait<1>();
        else                   cp_wait<0>();
        __syncthreads();   // stage kt ready; all warps done with stage kt-1 compute

        // prefetch stage kt+3 into buffer (kt+3)%4 == (kt-1)%4 (freed by the sync above)
        if (kt + 3 < NKT) {
            load_tile(smem + ((kt + 3) % NSTAGE) * STAGE_HALFS, gA, gB, kt + 3, tid);
            cp_commit();
        }

        const uint32_t a_base = smem_u32(smem + (kt % NSTAGE) * STAGE_HALFS);
        const uint32_t b_base = a_base + A_HALFS * 2;
#pragma unroll
        for (int kk = 0; kk < KT; kk += 16) {
            uint32_t af[2][4];
#pragma unroll
            for (int mi = 0; mi < 2; mi++) {
                int row = warpM + mi * 16 + (lane & 15);
                int col = kk + (lane >> 4) * 8;
                ldsm4(af[mi], a_base + (row * LDT + col) * 2);
            }
            uint32_t bf[4][4];
#pragma unroll
            for (int nj = 0; nj < 4; nj++) {
                int row = warpN + nj * 16 + (lane & 7) + ((lane >> 4) << 3);
                int col = kk + (((lane >> 3) & 1) << 3);
                ldsm4(bf[nj], b_base + (row * LDT + col) * 2);
            }
#pragma unroll
            for (int mi = 0; mi < 2; mi++)
#pragma unroll
                for (int ni = 0; ni < 8; ni++)
                    mma16816(acc[mi][ni], af[mi], &bf[ni >> 1][(ni & 1) * 2]);
        }
        __syncthreads();   // all warps done reading stage kt before it is refilled
    }

    // epilogue: fp32 out [T, N]
#pragma unroll
    for (int mi = 0; mi < 2; mi++) {
#pragma unroll
        for (int ni = 0; ni < 8; ni++) {
            size_t r = bm + warpM + mi * 16 + (lane >> 2);
            size_t col = bn + warpN + ni * 8 + (lane & 3) * 2;
            float2 lo = {acc[mi][ni][0], acc[mi][ni][1]};
            float2 hi = {acc[mi][ni][2], acc[mi][ni][3]};
            *(float2*)&C[r * NDIM + col] = lo;
            *(float2*)&C[(r + 8) * NDIM + col] = hi;
        }
    }
}

// ---------------- launch ----------------
extern "C" void kernel_launch(void* const* d_in, const int* in_sizes, int n_in,
                              void* d_out, int out_size) {
    const float* x     = (const float*)d_in[0];
    const int*   idxp  = (const int*)d_in[1];
    const float* cb    = (const float*)d_in[2];
    const float* norms = (const float*)d_in[3];
    const float* rot   = (const float*)d_in[4];
    float* out = (float*)d_out;

    cudaFuncSetAttribute(gemm_kernel, cudaFuncAttributeMaxDynamicSharedMemorySize, GEMM_SMEM);

    convert_x_kernel<<<4096, 256>>>(x);
    build_w_kernel<<<dim3(NDIM / 32, 32), 256>>>(idxp, cb, norms, rot);
    gemm_kernel<<<dim3(NDIM / 128, T_TOK / 128), 256, GEMM_SMEM>>>(out);
}

// round 17
// speedup vs baseline: 1.3348x; 1.1815x over previous
#include <cuda_runtime.h>
#include <cuda_fp16.h>
#include <cstdint>
#include <cstddef>

// out[t,n] = sum_k X[t,k] * W'[n,k]
// W' = dequant+rotate folded weights; GEMM on HMMA fp16/fp32-acc.
// R16: smem-BW model from R15 measurement (96 KB/SM/iter = 768cyc > HMMA 512cyc)
// -> 64x64 warp tiles (4 warps/CTA) halve LDSM traffic to 64 KB/SM/iter = 512cyc,
//    balancing smem feed with the HMMA floor. CTA 128x128 @ 2 CTA/SM kept (R12 lesson),
//    4-stage 16B cp.async pipeline kept (R15 win).

#define T_TOK 8192
#define KDIM  4096
#define NDIM  4096

__device__ __align__(1024) __half g_Xh[(size_t)T_TOK * KDIM]; // 64 MiB
__device__ __align__(1024) __half g_Wh[(size_t)NDIM * KDIM];  // 32 MiB

// ---------------- helpers ----------------
__device__ __forceinline__ uint32_t smem_u32(const void* p) {
    uint32_t a;
    asm("{ .reg .u64 t; cvta.to.shared.u64 t, %1; cvt.u32.u64 %0, t; }" : "=r"(a) : "l"(p));
    return a;
}
__device__ __forceinline__ void cp_async16(uint32_t s, const void* g) {
    asm volatile("cp.async.cg.shared.global [%0], [%1], 16;" :: "r"(s), "l"(g) : "memory");
}
__device__ __forceinline__ void cp_commit() { asm volatile("cp.async.commit_group;" ::: "memory"); }
template <int N> __device__ __forceinline__ void cp_wait() {
    asm volatile("cp.async.wait_group %0;" :: "n"(N) : "memory");
}
__device__ __forceinline__ void ldsm4(uint32_t* r, uint32_t addr) {
    asm volatile("ldmatrix.sync.aligned.m8n8.x4.shared.b16 {%0,%1,%2,%3}, [%4];"
                 : "=r"(r[0]), "=r"(r[1]), "=r"(r[2]), "=r"(r[3]) : "r"(addr));
}
__device__ __forceinline__ void mma16816(float* c, const uint32_t* a, const uint32_t* b) {
    asm volatile(
        "mma.sync.aligned.m16n8k16.row.col.f32.f16.f16.f32 "
        "{%0,%1,%2,%3}, {%4,%5,%6,%7}, {%8,%9}, {%0,%1,%2,%3};"
        : "+f"(c[0]), "+f"(c[1]), "+f"(c[2]), "+f"(c[3])
        : "r"(a[0]), "r"(a[1]), "r"(a[2]), "r"(a[3]), "r"(b[0]), "r"(b[1]));
}

// ---------------- kernel 1: X fp32 -> fp16 (74% HBM spec; leave it) ----------------
__global__ void convert_x_kernel(const float* __restrict__ x) {
    size_t i = (size_t)blockIdx.x * blockDim.x + threadIdx.x;
    const size_t stride = (size_t)gridDim.x * blockDim.x;
    const size_t n4 = (size_t)T_TOK * KDIM / 4;
    const float4* x4 = (const float4*)x;
    uint2* o = (uint2*)g_Xh;
    for (; i < n4; i += stride) {
        float4 v = x4[i];
        __half2 a = __floats2half2_rn(v.x, v.y);
        __half2 b = __floats2half2_rn(v.z, v.w);
        uint2 u;
        u.x = *(const uint32_t*)&a;
        u.y = *(const uint32_t*)&b;
        o[i] = u;
    }
}

// ---------------- kernel 2: build W' (unchanged, known good) ----------------
__global__ __launch_bounds__(256) void build_w_kernel(
    const int* __restrict__ idxp, const float* __restrict__ cb,
    const float* __restrict__ norms, const float* __restrict__ rot) {
    __shared__ float rot_s[64 * 128];
    __shared__ __half wc[32 * 128];
    __shared__ float cb_s[16];

    const int tid = threadIdx.x;
    const int g = blockIdx.y;
    const int n0 = blockIdx.x * 32;

    if (tid < 16) cb_s[tid] = cb[tid];
    __syncthreads();

    {
        const int row = tid >> 3, c = tid & 7;
        const int n = n0 + row;
        const float scale = norms[n * 32 + g] * 0.08838834764831845f;
        const int4* p = (const int4*)(idxp + (size_t)n * 2048 + g * 64 + c * 8);
        int4 v0 = p[0], v1 = p[1];
        int vs[8] = {v0.x, v0.y, v0.z, v0.w, v1.x, v1.y, v1.z, v1.w};
#pragma unroll
        for (int i = 0; i < 8; i++) {
            int j = c * 16 + i * 2;
            wc[row * 128 + j]     = __float2half(cb_s[vs[i] & 15] * scale);
            wc[row * 128 + j + 1] = __float2half(cb_s[(vs[i] >> 4) & 15] * scale);
        }
    }

    const int rq = tid >> 4;
    const int k0 = (tid & 15) * 8;
    float acc0[8], acc1[8];
#pragma unroll
    for (int i = 0; i < 8; i++) { acc0[i] = 0.f; acc1[i] = 0.f; }

    for (int jt = 0; jt < 2; jt++) {
        __syncthreads();
        const float4* gr = (const float4*)(rot + (size_t)g * 16384 + (size_t)jt * 8192);
        float4* rs4 = (float4*)rot_s;
#pragma unroll
        for (int i = 0; i < 8; i++) rs4[tid + i * 256] = gr[tid + i * 256];
        __syncthreads();
#pragma unroll 8
        for (int j = 0; j < 64; j++) {
            float w0 = __half2float(wc[rq * 128 + jt * 64 + j]);
            float w1 = __half2float(wc[(rq + 16) * 128 + jt * 64 + j]);
            float4 r0 = *(const float4*)&rot_s[j * 128 + k0];
            float4 r1 = *(const float4*)&rot_s[j * 128 + k0 + 4];
            acc0[0] += w0 * r0.x; acc0[1] += w0 * r0.y; acc0[2] += w0 * r0.z; acc0[3] += w0 * r0.w;
            acc0[4] += w0 * r1.x; acc0[5] += w0 * r1.y; acc0[6] += w0 * r1.z; acc0[7] += w0 * r1.w;
            acc1[0] += w1 * r0.x; acc1[1] += w1 * r0.y; acc1[2] += w1 * r0.z; acc1[3] += w1 * r0.w;
            acc1[4] += w1 * r1.x; acc1[5] += w1 * r1.y; acc1[6] += w1 * r1.z; acc1[7] += w1 * r1.w;
        }
    }

    {
        __half2 h0 = __floats2half2_rn(acc0[0], acc0[1]);
        __half2 h1 = __floats2half2_rn(acc0[2], acc0[3]);
        __half2 h2 = __floats2half2_rn(acc0[4], acc0[5]);
        __half2 h3 = __floats2half2_rn(acc0[6], acc0[7]);
        uint4 u = {*(uint32_t*)&h0, *(uint32_t*)&h1, *(uint32_t*)&h2, *(uint32_t*)&h3};
        *(uint4*)&g_Wh[(size_t)(n0 + rq) * KDIM + g * 128 + k0] = u;
    }
    {
        __half2 h0 = __floats2half2_rn(acc1[0], acc1[1]);
        __half2 h1 = __floats2half2_rn(acc1[2], acc1[3]);
        __half2 h2 = __floats2half2_rn(acc1[4], acc1[5]);
        __half2 h3 = __floats2half2_rn(acc1[6], acc1[7]);
        uint4 u = {*(uint32_t*)&h0, *(uint32_t*)&h1, *(uint32_t*)&h2, *(uint32_t*)&h3};
        *(uint4*)&g_Wh[(size_t)(n0 + rq + 16) * KDIM + g * 128 + k0] = u;
    }
}

// ---------------- kernel 3: GEMM C[T,N] = Xh @ Wh^T ----------------
// CTA 128x128, 128 threads (4 warps 2x2), warp tile 64x64, KT=32,
// 4-stage cp.async(16B) pipeline, dynamic smem, 2 CTA/SM.
#define LDT 40                     // 80B row stride: conflict-free ldsm, 16B-aligned
#define KT  32
#define NKT (KDIM / KT)            // 128
#define A_HALFS (128 * LDT)
#define B_HALFS (128 * LDT)
#define STAGE_HALFS (A_HALFS + B_HALFS)       // 10240 halfs = 20480 B
#define NSTAGE 4
#define GEMM_SMEM (NSTAGE * STAGE_HALFS * 2)  // 81920 B (x2 CTA = 160 KB < 228 KB)

__device__ __forceinline__ void load_tile(__half* sbase, const __half* __restrict__ gA,
                                          const __half* __restrict__ gB, int kt, int tid) {
    __half* sA = sbase;
    __half* sB = sbase + A_HALFS;
    // A: 128 rows x 4 chunks(16B) = 512 units; 4 per thread (128 threads)
#pragma unroll
    for (int i = 0; i < 4; i++) {
        int u = tid + i * 128;
        int row = u >> 2, c = u & 3;
        cp_async16(smem_u32(&sA[row * LDT + c * 8]), gA + (size_t)row * KDIM + kt * KT + c * 8);
    }
    // B: same shape
#pragma unroll
    for (int i = 0; i < 4; i++) {
        int u = tid + i * 128;
        int row = u >> 2, c = u & 3;
        cp_async16(smem_u32(&sB[row * LDT + c * 8]), gB + (size_t)row * KDIM + kt * KT + c * 8);
    }
}

__global__ __launch_bounds__(128, 2) void gemm_kernel(float* __restrict__ C) {
    extern __shared__ __half smem[];

    const int tid = threadIdx.x;
    const int wid = tid >> 5, lane = tid & 31;
    const int warpM = (wid >> 1) * 64;  // 2 warp-rows -> 128
    const int warpN = (wid & 1) * 64;   // 2 warp-cols -> 128
    const size_t bm = (size_t)blockIdx.y * 128;
    const size_t bn = (size_t)blockIdx.x * 128;

    const __half* gA = g_Xh + bm * KDIM;
    const __half* gB = g_Wh + bn * KDIM;

    float acc[4][8][4];
#pragma unroll
    for (int mi = 0; mi < 4; mi++)
#pragma unroll
        for (int ni = 0; ni < 8; ni++)
#pragma unroll
            for (int q = 0; q < 4; q++) acc[mi][ni][q] = 0.f;

    load_tile(smem + 0 * STAGE_HALFS, gA, gB, 0, tid); cp_commit();
    load_tile(smem + 1 * STAGE_HALFS, gA, gB, 1, tid); cp_commit();
    load_tile(smem + 2 * STAGE_HALFS, gA, gB, 2, tid); cp_commit();

    for (int kt = 0; kt < NKT; kt++) {
        // retire group kt: outstanding groups are kt .. min(kt+2, NKT-1)
        if (kt + 2 < NKT)      cp_wait<2>();
        else if (kt + 1 < NKT) cp_wait<1>();
        else                   cp_wait<0>();
        __syncthreads();   // stage kt ready; all warps done with stage kt-1 compute

        // prefetch stage kt+3 into buffer (kt+3)%4 == (kt-1)%4 (freed by the sync above)
        if (kt + 3 < NKT) {
            load_tile(smem + ((kt + 3) % NSTAGE) * STAGE_HALFS, gA, gB, kt + 3, tid);
            cp_commit();
        }

        const uint32_t a_base = smem_u32(smem + (kt % NSTAGE) * STAGE_HALFS);
        const uint32_t b_base = a_base + A_HALFS * 2;
#pragma unroll
        for (int kk = 0; kk < KT; kk += 16) {
            uint32_t af[4][4];
#pragma unroll
            for (int mi = 0; mi < 4; mi++) {
                int row = warpM + mi * 16 + (lane & 15);
                int col = kk + (lane >> 4) * 8;
                ldsm4(af[mi], a_base + (row * LDT + col) * 2);
            }
            uint32_t bf[4][4];
#pragma unroll
            for (int nj = 0; nj < 4; nj++) {
                int row = warpN + nj * 16 + (lane & 7) + ((lane >> 4) << 3);
                int col = kk + (((lane >> 3) & 1) << 3);
                ldsm4(bf[nj], b_base + (row * LDT + col) * 2);
            }
#pragma unroll
            for (int mi = 0; mi < 4; mi++)
#pragma unroll
                for (int ni = 0; ni < 8; ni++)
                    mma16816(acc[mi][ni], af[mi], &bf[ni >> 1][(ni & 1) * 2]);
        }
        __syncthreads();   // all warps done reading stage kt before it is refilled
    }

    // epilogue: fp32 out [T, N]
#pragma unroll
    for (int mi = 0; mi < 4; mi++) {
#pragma unroll
        for (int ni = 0; ni < 8; ni++) {
            size_t r = bm + warpM + mi * 16 + (lane >> 2);
            size_t col = bn + warpN + ni * 8 + (lane & 3) * 2;
            float2 lo = {acc[mi][ni][0], acc[mi][ni][1]};
            float2 hi = {acc[mi][ni][2], acc[mi][ni][3]};
            *(float2*)&C[r * NDIM + col] = lo;
            *(float2*)&C[(r + 8) * NDIM + col] = hi;
        }
    }
}

// ---------------- launch ----------------
extern "C" void kernel_launch(void* const* d_in, const int* in_sizes, int n_in,
                              void* d_out, int out_size) {
    const float* x     = (const float*)d_in[0];
    const int*   idxp  = (const int*)d_in[1];
    const float* cb    = (const float*)d_in[2];
    const float* norms = (const float*)d_in[3];
    const float* rot   = (const float*)d_in[4];
    float* out = (float*)d_out;

    cudaFuncSetAttribute(gemm_kernel, cudaFuncAttributeMaxDynamicSharedMemorySize, GEMM_SMEM);

    convert_x_kernel<<<4096, 256>>>(x);
    build_w_kernel<<<dim3(NDIM / 32, 32), 256>>>(idxp, cb, norms, rot);
    gemm_kernel<<<dim3(NDIM / 128, T_TOK / 128), 128, GEMM_SMEM>>>(out);
}